// round 4
// baseline (speedup 1.0000x reference)
#include <cuda_runtime.h>
#include <cstdint>

// out[n,o] = (sum_k xq[n,k]*wq[o,k]) * sx*sw + bias[o]
// xq = round_half_even(x/sx) clamped [-128,127], sx = max|x|/127 (same for w).
// lut[i][j] == (i-128)*(j-128) -> gather is algebraically int8 multiply.
// N = IN = OUT = 512. One persistent kernel: absmax -> quant -> split-K IMMA GEMM.

#define NN 512
#define KK 512
#define OO 512

// ---- device scratch (no allocations allowed) ----
__device__ int g_maxx;             // float bits of max|x| (monotone under atomicMax)
__device__ int g_maxw;             // float bits of max|w|
__device__ unsigned g_ctr;         // monotonic grid-barrier counter (never reset)
__device__ int g_xa[NN * KK / 4];  // A fragments (m16n8k32): [rt16][kt32] x 32 lanes x 4 ints
__device__ int g_wb[OO * KK / 4];  // B fragments: [ct8][kt32] x 32 lanes x 2 ints

// ------------------------------------------------------------------
// fragment-layout address helpers (validated in rounds 2-3)
// A frag (row-major 16x32 s8): lane = (row%8)*4 + kw%4, j = row/8 + 2*(kw/4)
// B frag (col-major 32x8 s8):  lane = (col%8)*4 + kw%4, j = kw/4
// ------------------------------------------------------------------
__device__ __forceinline__ int xaddr(int r, int k0) {
    int rt = r >> 4, rr = r & 15, kt = k0 >> 5, kw = (k0 & 31) >> 2;
    int l = ((rr & 7) << 2) + (kw & 3);
    int j = (rr >> 3) + ((kw >> 2) << 1);
    return ((rt * 16 + kt) * 32 + l) * 4 + j;
}
__device__ __forceinline__ int waddr(int o, int k0) {
    int ct = o >> 3, cc = o & 7, kt = k0 >> 5, kw = (k0 & 31) >> 2;
    int l = (cc << 2) + (kw & 3);
    int j = kw >> 2;
    return ((ct * 16 + kt) * 32 + l) * 2 + j;
}

__device__ __forceinline__ int quant1(float v, float s) {
    int q = __float2int_rn(v / s);          // IEEE div + rn matches jnp.round
    q = max(-128, min(127, q));
    return q & 0xFF;
}
__device__ __forceinline__ int pack4(float4 v, float s) {
    return quant1(v.x, s) | (quant1(v.y, s) << 8) |
           (quant1(v.z, s) << 16) | (quant1(v.w, s) << 24);
}

__device__ __forceinline__ void mma_s8(int* c, const int4 a, const int2 b) {
    asm volatile(
        "mma.sync.aligned.m16n8k32.row.col.s32.s8.s8.s32 "
        "{%0,%1,%2,%3}, {%4,%5,%6,%7}, {%8,%9}, {%0,%1,%2,%3};"
        : "+r"(c[0]), "+r"(c[1]), "+r"(c[2]), "+r"(c[3])
        : "r"(a.x), "r"(a.y), "r"(a.z), "r"(a.w), "r"(b.x), "r"(b.y));
}

// Grid-wide barrier: monotonic counter, each instance adds exactly 128 (one
// per block). Every replay adds a multiple of 128, so the ceiling arithmetic
// is replay-safe with no reset.
__device__ __forceinline__ void grid_barrier(int tid) {
    __threadfence();
    __syncthreads();
    if (tid == 0) {
        unsigned arr = atomicAdd(&g_ctr, 1u) + 1u;
        unsigned target = ((arr + 127u) >> 7) << 7;   // ceil to multiple of 128
        while (*(volatile unsigned*)&g_ctr < target) { }
        __threadfence();
    }
    __syncthreads();
}

// ------------------------------------------------------------------
// 128 blocks x 512 threads, exactly 1 block/SM -> co-residency guaranteed.
//   Phase A: absmax of x and w (data held in registers)
//   Phase B: quantize from registers into fragment-ordered scratch
//   Phase C: split-K IMMA GEMM: 2048 warps; warp pair (2j,2j+1) of a block
//            shares one 16x16 output tile, each covering 8 of 16 k-tiles;
//            exact int32 reduction through smem.
// ------------------------------------------------------------------
__global__ __launch_bounds__(512, 1)
void fused_kernel(const float4* __restrict__ x, const float4* __restrict__ w,
                  const float* __restrict__ bias, float* __restrict__ out) {
    __shared__ float smx[16], smw[16];
    __shared__ int   sred[8][32][8];          // 8 tile-pairs per block
    const int tid = threadIdx.x;
    const int t   = blockIdx.x * 512 + tid;   // 0..65535

    // ---------- Phase A: absmax ----------
    float4 xv = x[t];
    float4 wv = w[t];

    float mx = fmaxf(fmaxf(fabsf(xv.x), fabsf(xv.y)),
                     fmaxf(fabsf(xv.z), fabsf(xv.w)));
    float mw = fmaxf(fmaxf(fabsf(wv.x), fabsf(wv.y)),
                     fmaxf(fabsf(wv.z), fabsf(wv.w)));
    #pragma unroll
    for (int o = 16; o > 0; o >>= 1) {
        mx = fmaxf(mx, __shfl_xor_sync(0xFFFFFFFFu, mx, o));
        mw = fmaxf(mw, __shfl_xor_sync(0xFFFFFFFFu, mw, o));
    }
    if ((tid & 31) == 0) { smx[tid >> 5] = mx; smw[tid >> 5] = mw; }
    __syncthreads();
    if (tid == 0) {
        float bx = smx[0], bw = smw[0];
        #pragma unroll
        for (int i = 1; i < 16; ++i) { bx = fmaxf(bx, smx[i]); bw = fmaxf(bw, smw[i]); }
        atomicMax(&g_maxx, __float_as_int(bx));
        atomicMax(&g_maxw, __float_as_int(bw));
    }
    grid_barrier(tid);

    // ---------- Phase B: quantize from registers ----------
    const float sx = __int_as_float(*(volatile int*)&g_maxx) / 127.0f;
    const float sw = __int_as_float(*(volatile int*)&g_maxw) / 127.0f;
    {
        int r = t >> 7, k0 = (t & 127) << 2;
        g_xa[xaddr(r, k0)] = pack4(xv, sx);
        g_wb[waddr(r, k0)] = pack4(wv, sw);
    }
    grid_barrier(tid);

    // ---------- Phase C: split-K IMMA GEMM ----------
    const int wid  = tid >> 5;
    const int lane = tid & 31;
    const int gw   = blockIdx.x * 16 + wid;   // 0..2047
    const int tile = gw >> 1;                 // 0..1023 (16x16 tiles)
    const int kh   = gw & 1;                  // K half
    const int rt   = tile >> 5;               // 0..31
    const int ct0  = (tile & 31) << 1;        // 0..62

    const int4* __restrict__ XA = (const int4*)g_xa;
    const int2* __restrict__ WB = (const int2*)g_wb;

    int acc[2][4];
    #pragma unroll
    for (int n = 0; n < 2; ++n)
        #pragma unroll
        for (int j = 0; j < 4; ++j) acc[n][j] = 0;

    #pragma unroll
    for (int kk = 0; kk < 8; ++kk) {
        int kt = kh * 8 + kk;
        int4 a  = XA[(rt * 16 + kt) * 32 + lane];
        int2 b0 = WB[((ct0 + 0) * 16 + kt) * 32 + lane];
        int2 b1 = WB[((ct0 + 1) * 16 + kt) * 32 + lane];
        mma_s8(acc[0], a, b0);
        mma_s8(acc[1], a, b1);
    }

    // exact int32 reduction across the K-half pair (same block)
    if (kh) {
        #pragma unroll
        for (int n = 0; n < 2; ++n)
            #pragma unroll
            for (int j = 0; j < 4; ++j)
                sred[wid >> 1][lane][n * 4 + j] = acc[n][j];
    }
    __syncthreads();
    if (!kh) {
        #pragma unroll
        for (int n = 0; n < 2; ++n)
            #pragma unroll
            for (int j = 0; j < 4; ++j)
                acc[n][j] += sred[wid >> 1][lane][n * 4 + j];

        const float sc = sx * sw;
        const int g   = lane >> 2;       // row within tile
        const int tig = lane & 3;        // col pair within 8-col tile
        #pragma unroll
        for (int n = 0; n < 2; ++n) {
            int col = (ct0 + n) * 8 + tig * 2;
            float2 bb = *(const float2*)&bias[col];
            int row = rt * 16 + g;
            float2 v0 = { (float)acc[n][0] * sc + bb.x,
                          (float)acc[n][1] * sc + bb.y };
            float2 v1 = { (float)acc[n][2] * sc + bb.x,
                          (float)acc[n][3] * sc + bb.y };
            *(float2*)&out[row * OO + col]       = v0;
            *(float2*)&out[(row + 8) * OO + col] = v1;
        }
    }
}

// ------------------------------------------------------------------
extern "C" void kernel_launch(void* const* d_in, const int* in_sizes, int n_in,
                              void* d_out, int out_size) {
    const float* x    = (const float*)d_in[0];   // [512,512]
    const float* w    = (const float*)d_in[1];   // [512,512]
    const float* bias = (const float*)d_in[2];   // [512]
    float* out = (float*)d_out;

    fused_kernel<<<128, 512>>>((const float4*)x, (const float4*)w, bias, out);
}

// round 5
// speedup vs baseline: 1.1032x; 1.1032x over previous
#include <cuda_runtime.h>
#include <cstdint>

// out[n,o] = (sum_k xq[n,k]*wq[o,k]) * sx*sw + bias[o]
// xq = round_half_even(x/sx) clamped [-128,127], sx = max|x|/127 (same for w).
// lut[i][j] == (i-128)*(j-128) -> gather is algebraically int8 multiply.
// N = IN = OUT = 512.
// One persistent kernel, 256 blocks x 256 thr (2 blocks/SM co-resident):
//   absmax -> quant(frag layout) -> IMMA GEMM (warp tile 16x8, full K).

#define NN 512
#define KK 512
#define OO 512

// ---- device scratch (no allocations allowed) ----
__device__ int g_maxx;             // float bits of max|x| (monotone under atomicMax)
__device__ int g_maxw;             // float bits of max|w|
__device__ unsigned g_ctr;         // monotonic grid-barrier counter (never reset)
__device__ int g_xa[NN * KK / 4];  // A fragments (m16n8k32): [rt16][kt32] x 32 lanes x 4 ints
__device__ int g_wb[OO * KK / 4];  // B fragments: [ct8][kt32] x 32 lanes x 2 ints

// ------------------------------------------------------------------
// fragment-layout address helpers (validated rounds 2-4)
// A frag (row-major 16x32 s8): lane = (row%8)*4 + kw%4, j = row/8 + 2*(kw/4)
// B frag (col-major 32x8 s8):  lane = (col%8)*4 + kw%4, j = kw/4
// ------------------------------------------------------------------
__device__ __forceinline__ int xaddr(int r, int k0) {
    int rt = r >> 4, rr = r & 15, kt = k0 >> 5, kw = (k0 & 31) >> 2;
    int l = ((rr & 7) << 2) + (kw & 3);
    int j = (rr >> 3) + ((kw >> 2) << 1);
    return ((rt * 16 + kt) * 32 + l) * 4 + j;
}
__device__ __forceinline__ int waddr(int o, int k0) {
    int ct = o >> 3, cc = o & 7, kt = k0 >> 5, kw = (k0 & 31) >> 2;
    int l = (cc << 2) + (kw & 3);
    int j = kw >> 2;
    return ((ct * 16 + kt) * 32 + l) * 2 + j;
}

// quantize via reciprocal-multiply: inv = 127/max (one div), q = rn(v*inv)
__device__ __forceinline__ int quant1(float v, float inv) {
    int q = __float2int_rn(v * inv);
    q = max(-128, min(127, q));
    return q & 0xFF;
}
__device__ __forceinline__ int pack4(float4 v, float inv) {
    return quant1(v.x, inv) | (quant1(v.y, inv) << 8) |
           (quant1(v.z, inv) << 16) | (quant1(v.w, inv) << 24);
}

__device__ __forceinline__ void mma_s8(int* c, const int4 a, const int2 b) {
    asm volatile(
        "mma.sync.aligned.m16n8k32.row.col.s32.s8.s8.s32 "
        "{%0,%1,%2,%3}, {%4,%5,%6,%7}, {%8,%9}, {%0,%1,%2,%3};"
        : "+r"(c[0]), "+r"(c[1]), "+r"(c[2]), "+r"(c[3])
        : "r"(a.x), "r"(a.y), "r"(a.z), "r"(a.w), "r"(b.x), "r"(b.y));
}

// Grid-wide barrier: monotonic counter, each instance adds exactly 256 (one
// per block). Every replay adds a multiple of 256, so the ceiling arithmetic
// is replay-safe with no reset. Requires all 256 blocks co-resident:
// guaranteed by __launch_bounds__(256,2) (2 blocks/SM x 148 SMs = 296 >= 256).
__device__ __forceinline__ void grid_barrier(int tid) {
    __threadfence();
    __syncthreads();
    if (tid == 0) {
        unsigned arr = atomicAdd(&g_ctr, 1u) + 1u;
        unsigned target = ((arr + 255u) >> 8) << 8;   // ceil to multiple of 256
        while (*(volatile unsigned*)&g_ctr < target) { }
        __threadfence();
    }
    __syncthreads();
}

// ------------------------------------------------------------------
__global__ __launch_bounds__(256, 2)
void fused_kernel(const float4* __restrict__ x, const float4* __restrict__ w,
                  const float* __restrict__ bias, float* __restrict__ out) {
    __shared__ float smx[8], smw[8];
    const int tid = threadIdx.x;
    const int t   = blockIdx.x * 256 + tid;   // 0..65535

    // ---------- Phase A: absmax (data stays in registers) ----------
    float4 xv = x[t];
    float4 wv = w[t];

    float mx = fmaxf(fmaxf(fabsf(xv.x), fabsf(xv.y)),
                     fmaxf(fabsf(xv.z), fabsf(xv.w)));
    float mw = fmaxf(fmaxf(fabsf(wv.x), fabsf(wv.y)),
                     fmaxf(fabsf(wv.z), fabsf(wv.w)));
    #pragma unroll
    for (int o = 16; o > 0; o >>= 1) {
        mx = fmaxf(mx, __shfl_xor_sync(0xFFFFFFFFu, mx, o));
        mw = fmaxf(mw, __shfl_xor_sync(0xFFFFFFFFu, mw, o));
    }
    if ((tid & 31) == 0) { smx[tid >> 5] = mx; smw[tid >> 5] = mw; }
    __syncthreads();
    if (tid == 0) {
        float bx = smx[0], bw = smw[0];
        #pragma unroll
        for (int i = 1; i < 8; ++i) { bx = fmaxf(bx, smx[i]); bw = fmaxf(bw, smw[i]); }
        atomicMax(&g_maxx, __float_as_int(bx));
        atomicMax(&g_maxw, __float_as_int(bw));
    }
    grid_barrier(tid);

    // ---------- Phase B: quantize from registers ----------
    const float fmx = __int_as_float(*(volatile int*)&g_maxx);
    const float fmw = __int_as_float(*(volatile int*)&g_maxw);
    const float invx = 127.0f / fmx;          // one div per tensor
    const float invw = 127.0f / fmw;
    {
        int r = t >> 7, k0 = (t & 127) << 2;
        g_xa[xaddr(r, k0)] = pack4(xv, invx);
        g_wb[waddr(r, k0)] = pack4(wv, invw);
    }
    grid_barrier(tid);

    // ---------- Phase C: IMMA GEMM, warp tile 16(M) x 8(N), full K ----------
    const int wid  = tid >> 5;
    const int lane = tid & 31;
    const int gw   = blockIdx.x * 8 + wid;    // 0..2047
    const int rt   = gw >> 6;                 // 0..31  (16-row tile)
    const int ct   = gw & 63;                 // 0..63  (8-col tile)

    const int4* __restrict__ XA = (const int4*)g_xa;
    const int2* __restrict__ WB = (const int2*)g_wb;

    int acc[4] = {0, 0, 0, 0};

    #pragma unroll
    for (int kt = 0; kt < 16; ++kt) {
        int4 a = XA[(rt * 16 + kt) * 32 + lane];
        int2 b = WB[(ct * 16 + kt) * 32 + lane];
        mma_s8(acc, a, b);
    }

    const float sc = (fmx / 127.0f) * (fmw / 127.0f);
    const int g   = lane >> 2;       // row within tile
    const int tig = lane & 3;        // col pair
    {
        int col = ct * 8 + tig * 2;
        float2 bb = *(const float2*)&bias[col];
        int row = rt * 16 + g;
        float2 v0 = { (float)acc[0] * sc + bb.x, (float)acc[1] * sc + bb.y };
        float2 v1 = { (float)acc[2] * sc + bb.x, (float)acc[3] * sc + bb.y };
        *(float2*)&out[row * OO + col]       = v0;
        *(float2*)&out[(row + 8) * OO + col] = v1;
    }
}

// ------------------------------------------------------------------
extern "C" void kernel_launch(void* const* d_in, const int* in_sizes, int n_in,
                              void* d_out, int out_size) {
    const float* x    = (const float*)d_in[0];   // [512,512]
    const float* w    = (const float*)d_in[1];   // [512,512]
    const float* bias = (const float*)d_in[2];   // [512]
    float* out = (float*)d_out;

    fused_kernel<<<256, 256>>>((const float4*)x, (const float4*)w, bias, out);
}

// round 6
// speedup vs baseline: 1.1527x; 1.0449x over previous
#include <cuda_runtime.h>
#include <cstdint>

// out[n,o] = (sum_k xq[n,k]*wq[o,k]) * sx*sw + bias[o]
// xq = round(x * 127/max|x|) clamped [-128,127]; same for w.
// lut[i][j] == (i-128)*(j-128) -> gather is algebraically int8 multiply.
// N = IN = OUT = 512.
// K1: absmax -> (1 grid barrier) -> quant into mma fragment layout.
// K2: IMMA GEMM, block tile 32x32, single wave.

#define NN 512
#define KK 512
#define OO 512

// ---- device scratch (no allocations allowed) ----
__device__ int g_maxx;             // float bits of max|x| (monotone under atomicMax)
__device__ int g_maxw;             // float bits of max|w|
__device__ unsigned g_ctr;         // monotonic grid-barrier counter (never reset)
__device__ int g_xa[NN * KK / 4];  // A fragments (m16n8k32): [rt16][kt32] x 32 lanes x 4 ints
__device__ int g_wb[OO * KK / 4];  // B fragments: [ct8][kt32] x 32 lanes x 2 ints

// ------------------------------------------------------------------
// fragment-layout address helpers (validated rounds 2-5)
// A frag (row-major 16x32 s8): lane = (row%8)*4 + kw%4, j = row/8 + 2*(kw/4)
// B frag (col-major 32x8 s8):  lane = (col%8)*4 + kw%4, j = kw/4
// ------------------------------------------------------------------
__device__ __forceinline__ int xaddr(int r, int k0) {
    int rt = r >> 4, rr = r & 15, kt = k0 >> 5, kw = (k0 & 31) >> 2;
    int l = ((rr & 7) << 2) + (kw & 3);
    int j = (rr >> 3) + ((kw >> 2) << 1);
    return ((rt * 16 + kt) * 32 + l) * 4 + j;
}
__device__ __forceinline__ int waddr(int o, int k0) {
    int ct = o >> 3, cc = o & 7, kt = k0 >> 5, kw = (k0 & 31) >> 2;
    int l = (cc << 2) + (kw & 3);
    int j = kw >> 2;
    return ((ct * 16 + kt) * 32 + l) * 2 + j;
}

// quantize via reciprocal-multiply: inv = 127/max (one div), q = rn(v*inv)
__device__ __forceinline__ int quant1(float v, float inv) {
    int q = __float2int_rn(v * inv);
    q = max(-128, min(127, q));
    return q & 0xFF;
}
__device__ __forceinline__ int pack4(float4 v, float inv) {
    return quant1(v.x, inv) | (quant1(v.y, inv) << 8) |
           (quant1(v.z, inv) << 16) | (quant1(v.w, inv) << 24);
}

__device__ __forceinline__ void mma_s8(int* c, const int4 a, const int2 b) {
    asm volatile(
        "mma.sync.aligned.m16n8k32.row.col.s32.s8.s8.s32 "
        "{%0,%1,%2,%3}, {%4,%5,%6,%7}, {%8,%9}, {%0,%1,%2,%3};"
        : "+r"(c[0]), "+r"(c[1]), "+r"(c[2]), "+r"(c[3])
        : "r"(a.x), "r"(a.y), "r"(a.z), "r"(a.w), "r"(b.x), "r"(b.y));
}

// ------------------------------------------------------------------
// K1: absmax + quantize. 256 blocks x 256 threads, 2 blocks/SM co-resident
// (guaranteed by __launch_bounds__(256,2): 296 slots >= 256 blocks).
// One grid barrier: monotonic counter, +256 per launch -> replay-safe.
// ------------------------------------------------------------------
__global__ __launch_bounds__(256, 2)
void quant_kernel(const float4* __restrict__ x, const float4* __restrict__ w) {
    __shared__ float smx[8], smw[8];
    const int tid = threadIdx.x;
    const int t   = blockIdx.x * 256 + tid;   // 0..65535

    // ---- absmax (data stays in registers) ----
    float4 xv = x[t];
    float4 wv = w[t];

    float mx = fmaxf(fmaxf(fabsf(xv.x), fabsf(xv.y)),
                     fmaxf(fabsf(xv.z), fabsf(xv.w)));
    float mw = fmaxf(fmaxf(fabsf(wv.x), fabsf(wv.y)),
                     fmaxf(fabsf(wv.z), fabsf(wv.w)));
    #pragma unroll
    for (int o = 16; o > 0; o >>= 1) {
        mx = fmaxf(mx, __shfl_xor_sync(0xFFFFFFFFu, mx, o));
        mw = fmaxf(mw, __shfl_xor_sync(0xFFFFFFFFu, mw, o));
    }
    if ((tid & 31) == 0) { smx[tid >> 5] = mx; smw[tid >> 5] = mw; }
    __syncthreads();

    // ---- grid barrier (thread 0 only does the heavy part) ----
    if (tid == 0) {
        float bx = smx[0], bw = smw[0];
        #pragma unroll
        for (int i = 1; i < 8; ++i) { bx = fmaxf(bx, smx[i]); bw = fmaxf(bw, smw[i]); }
        atomicMax(&g_maxx, __float_as_int(bx));
        atomicMax(&g_maxw, __float_as_int(bw));
        __threadfence();   // order atomicMax before the arrive
        unsigned arr = atomicAdd(&g_ctr, 1u) + 1u;
        unsigned target = ((arr + 255u) >> 8) << 8;   // ceil to multiple of 256
        while (*(volatile unsigned*)&g_ctr < target) { }
        __threadfence();   // acquire: see all blocks' atomicMax results
    }
    __syncthreads();

    // ---- quantize from registers into fragment layout ----
    const float invx = 127.0f / __int_as_float(*(volatile int*)&g_maxx);
    const float invw = 127.0f / __int_as_float(*(volatile int*)&g_maxw);
    {
        int r = t >> 7, k0 = (t & 127) << 2;
        g_xa[xaddr(r, k0)] = pack4(xv, invx);
        g_wb[waddr(r, k0)] = pack4(wv, invw);
    }
}

// ------------------------------------------------------------------
// K2: IMMA GEMM. 256 blocks x 256 threads, single wave (occupancy 2).
// Block tile 32(M) x 32(N): 8 warps as 2rt x 4ct of 16x8 warp tiles, full K.
// A fragments L1-shared by 4 warps, B by 2 warps.
// ------------------------------------------------------------------
__global__ __launch_bounds__(256, 2)
void gemm_kernel(const float* __restrict__ bias, float* __restrict__ out) {
    const int tid  = threadIdx.x;
    const int wid  = tid >> 5;
    const int lane = tid & 31;
    const int rt   = (blockIdx.x >> 4) * 2 + (wid >> 2);  // 0..31
    const int ct   = (blockIdx.x & 15) * 4 + (wid & 3);   // 0..63

    const int4* __restrict__ XA = (const int4*)g_xa;
    const int2* __restrict__ WB = (const int2*)g_wb;

    int acc[4] = {0, 0, 0, 0};

    #pragma unroll
    for (int kt = 0; kt < 16; ++kt) {
        int4 a = XA[(rt * 16 + kt) * 32 + lane];
        int2 b = WB[(ct * 16 + kt) * 32 + lane];
        mma_s8(acc, a, b);
    }

    const float fmx = __int_as_float(g_maxx);
    const float fmw = __int_as_float(g_maxw);
    const float sc  = (fmx / 127.0f) * (fmw / 127.0f);
    const int g   = lane >> 2;       // row within tile
    const int tig = lane & 3;        // col pair
    {
        int col = ct * 8 + tig * 2;
        float2 bb = *(const float2*)&bias[col];
        int row = rt * 16 + g;
        float2 v0 = { (float)acc[0] * sc + bb.x, (float)acc[1] * sc + bb.y };
        float2 v1 = { (float)acc[2] * sc + bb.x, (float)acc[3] * sc + bb.y };
        *(float2*)&out[row * OO + col]       = v0;
        *(float2*)&out[(row + 8) * OO + col] = v1;
    }
}

// ------------------------------------------------------------------
extern "C" void kernel_launch(void* const* d_in, const int* in_sizes, int n_in,
                              void* d_out, int out_size) {
    const float* x    = (const float*)d_in[0];   // [512,512]
    const float* w    = (const float*)d_in[1];   // [512,512]
    const float* bias = (const float*)d_in[2];   // [512]
    float* out = (float*)d_out;

    quant_kernel<<<256, 256>>>((const float4*)x, (const float4*)w);
    gemm_kernel<<<256, 256>>>(bias, out);
}